// round 15
// baseline (speedup 1.0000x reference)
#include <cuda_runtime.h>
#include <cstdint>

#define N_LEVELS 12
#define LOG2_T 19
#define TBL_SIZE (1u << LOG2_T)
#define TMASK (TBL_SIZE - 1u)
#define N_FEATURES 2
#define N_PTS 1048576

#define P1 2654435761u
#define P2 805459861u

#define SORT_RES 32
#define NB (SORT_RES * SORT_RES * SORT_RES)   // 32768 buckets, key = 15 bits

#define HIST_PPT 2     // points per thread in hist
#define SCAT_PPT 4     // points per thread in scatter

__device__ uint32_t g_kr[N_PTS];      // packed: key | (rank << 15)
__device__ uint32_t g_hist[NB];
__device__ uint32_t g_off[NB];
__device__ float4   g_xs[N_PTS];      // sorted points: (x, y, z, bits(orig_idx))

__device__ __forceinline__ uint32_t part1by2(uint32_t v) {
    v &= 0x3FFu;
    v = (v | (v << 16)) & 0x030000FFu;
    v = (v | (v << 8))  & 0x0300F00Fu;
    v = (v | (v << 4))  & 0x030C30C3u;
    v = (v | (v << 2))  & 0x09249249u;
    return v;
}

__device__ __forceinline__ uint32_t bucket_key(float px, float py, float pz) {
    uint32_t cx = min((uint32_t)(px * (float)SORT_RES), (uint32_t)(SORT_RES - 1));
    uint32_t cy = min((uint32_t)(py * (float)SORT_RES), (uint32_t)(SORT_RES - 1));
    uint32_t cz = min((uint32_t)(pz * (float)SORT_RES), (uint32_t)(SORT_RES - 1));
    return part1by2(cx) | (part1by2(cy) << 1) | (part1by2(cz) << 2);
}

// Key + intra-bucket rank (atomicAdd return), packed into one word.
__global__ void hist_kernel(const float* __restrict__ x) {
    const int t = blockIdx.x * blockDim.x + threadIdx.x;
    const int H = N_PTS / HIST_PPT;
    if (t >= H) return;

    const int i0 = t;
    const int i1 = t + H;

    const float ax = x[3 * i0 + 0];
    const float ay = x[3 * i0 + 1];
    const float az = x[3 * i0 + 2];
    const float bx = x[3 * i1 + 0];
    const float by = x[3 * i1 + 1];
    const float bz = x[3 * i1 + 2];

    const uint32_t ka = bucket_key(ax, ay, az);
    const uint32_t kb = bucket_key(bx, by, bz);

    const uint32_t ra = atomicAdd(&g_hist[ka], 1u);
    const uint32_t rb = atomicAdd(&g_hist[kb], 1u);

    g_kr[i0] = ka | (ra << 15);
    g_kr[i1] = kb | (rb << 15);
}

// Bank-swizzled smem index (round 5 notes).
__device__ __forceinline__ uint32_t swz(uint32_t i) {
    return (i & ~31u) | ((i + (i >> 5)) & 31u);
}

// Exclusive scan of 32768 bins; all global traffic coalesced via 128KB smem.
__global__ void __launch_bounds__(1024) scan_kernel() {
    extern __shared__ uint32_t sh[];
    __shared__ uint32_t s[1024];
    const int t = threadIdx.x;

    #pragma unroll
    for (int k = 0; k < 32; k++) {
        uint32_t i = (uint32_t)(k * 1024 + t);
        sh[swz(i)] = g_hist[i];
    }
    __syncthreads();

    uint32_t vals[32];
    uint32_t tot = 0;
    #pragma unroll
    for (int k = 0; k < 32; k++) {
        vals[k] = sh[t * 32 + ((k + t) & 31)];
        tot += vals[k];
    }
    s[t] = tot;
    __syncthreads();

    for (int off = 1; off < 1024; off <<= 1) {
        uint32_t v = (t >= off) ? s[t - off] : 0u;
        __syncthreads();
        s[t] += v;
        __syncthreads();
    }

    uint32_t run = s[t] - tot;
    #pragma unroll
    for (int k = 0; k < 32; k++) {
        sh[t * 32 + ((k + t) & 31)] = run;
        run += vals[k];
    }
    __syncthreads();

    #pragma unroll
    for (int k = 0; k < 32; k++) {
        uint32_t i = (uint32_t)(k * 1024 + t);
        g_off[i] = sh[swz(i)];
    }
}

// Atomic-free scatter, 4 points per thread. Rank order from hist's atomics is
// nondeterministic, but g_xs is always the same multiset and every point's
// output goes to its own original slot -> d_out is order-invariant.
__global__ void scatter_kernel(const float* __restrict__ x) {
    const int t = blockIdx.x * blockDim.x + threadIdx.x;
    const int Q = N_PTS / SCAT_PPT;
    if (t >= Q) return;

    int idx[SCAT_PPT];
    uint32_t kr[SCAT_PPT];
    #pragma unroll
    for (int k = 0; k < SCAT_PPT; k++) {
        idx[k] = t + k * Q;
        kr[k] = g_kr[idx[k]];
    }

    uint32_t base[SCAT_PPT];
    #pragma unroll
    for (int k = 0; k < SCAT_PPT; k++)
        base[k] = g_off[kr[k] & (NB - 1u)];

    float4 p[SCAT_PPT];
    #pragma unroll
    for (int k = 0; k < SCAT_PPT; k++) {
        p[k].x = x[3 * idx[k] + 0];
        p[k].y = x[3 * idx[k] + 1];
        p[k].z = x[3 * idx[k] + 2];
        p[k].w = __uint_as_float((uint32_t)idx[k]);
    }

    #pragma unroll
    for (int k = 0; k < SCAT_PPT; k++)
        __stcs(&g_xs[base[k] + (kr[k] >> 15)], p[k]);
}

__global__ void __launch_bounds__(256, 6) hashgrid_kernel(
    const float* __restrict__ tables,
    float* __restrict__ out)
{
    const int i = blockIdx.x * blockDim.x + threadIdx.x;
    if (i >= N_PTS) return;

    // One coalesced 16B load delivers coords + original index.
    const float4 p = __ldg(&g_xs[i]);
    const float px = p.x;
    const float py = p.y;
    const float pz = p.z;
    const uint32_t j = __float_as_uint(p.w);

    float4* __restrict__ o = (float4*)(out + (size_t)j * (N_LEVELS * N_FEATURES));

    const int res_host[N_LEVELS] = {16, 22, 30, 42, 58, 80, 110, 152, 210, 290, 400, 553};

    float pend0 = 0.0f, pend1 = 0.0f;

    #pragma unroll
    for (int l = 0; l < N_LEVELS; l++) {
        const float res = (float)res_host[l];

        const float sx = px * res;
        const float sy = py * res;
        const float sz = pz * res;
        const float fx = floorf(sx);
        const float fy = floorf(sy);
        const float fz = floorf(sz);
        const float wx = sx - fx;
        const float wy = sy - fy;
        const float wz = sz - fz;

        const uint32_t xi = (uint32_t)fx;
        const uint32_t yi = (uint32_t)fy;
        const uint32_t zi = (uint32_t)fz;

        const uint32_t hy0 = yi * P1;
        const uint32_t hy1 = (yi + 1u) * P1;
        const uint32_t hz0 = zi * P2;
        const uint32_t hz1 = (zi + 1u) * P2;
        const uint32_t x0 = xi;
        const uint32_t x1 = xi + 1u;

        const uint32_t m00 = hy0 ^ hz0;
        const uint32_t m10 = hy1 ^ hz0;
        const uint32_t m01 = hy0 ^ hz1;
        const uint32_t m11 = hy1 ^ hz1;

        const uint32_t i000 = (x0 ^ m00) & TMASK;
        const uint32_t i010 = (x0 ^ m10) & TMASK;
        const uint32_t i001 = (x0 ^ m01) & TMASK;
        const uint32_t i011 = (x0 ^ m11) & TMASK;

        const float2* __restrict__ tab =
            (const float2*)(tables + (size_t)l * TBL_SIZE * N_FEATURES);

        float2 f000, f100, f010, f110, f001, f101, f011, f111;

        if ((xi & 1u) == 0u) {
            // x1 = x0 | 1: each dx-pair is consecutive entries {2k,2k+1}
            // -> one aligned float4 per pair.
            const float4* __restrict__ t4 = (const float4*)tab;
            const float4 v00 = __ldg(t4 + (i000 >> 1));
            const float4 v10 = __ldg(t4 + (i010 >> 1));
            const float4 v01 = __ldg(t4 + (i001 >> 1));
            const float4 v11 = __ldg(t4 + (i011 >> 1));

            const bool s00 = (i000 & 1u) != 0u;
            const bool s10 = (i010 & 1u) != 0u;
            const bool s01 = (i001 & 1u) != 0u;
            const bool s11 = (i011 & 1u) != 0u;

            f000 = s00 ? make_float2(v00.z, v00.w) : make_float2(v00.x, v00.y);
            f100 = s00 ? make_float2(v00.x, v00.y) : make_float2(v00.z, v00.w);
            f010 = s10 ? make_float2(v10.z, v10.w) : make_float2(v10.x, v10.y);
            f110 = s10 ? make_float2(v10.x, v10.y) : make_float2(v10.z, v10.w);
            f001 = s01 ? make_float2(v01.z, v01.w) : make_float2(v01.x, v01.y);
            f101 = s01 ? make_float2(v01.x, v01.y) : make_float2(v01.z, v01.w);
            f011 = s11 ? make_float2(v11.z, v11.w) : make_float2(v11.x, v11.y);
            f111 = s11 ? make_float2(v11.x, v11.y) : make_float2(v11.z, v11.w);
        } else {
            const uint32_t i100 = (x1 ^ m00) & TMASK;
            const uint32_t i110 = (x1 ^ m10) & TMASK;
            const uint32_t i101 = (x1 ^ m01) & TMASK;
            const uint32_t i111 = (x1 ^ m11) & TMASK;

            f000 = __ldg(tab + i000);
            f100 = __ldg(tab + i100);
            f010 = __ldg(tab + i010);
            f110 = __ldg(tab + i110);
            f001 = __ldg(tab + i001);
            f101 = __ldg(tab + i101);
            f011 = __ldg(tab + i011);
            f111 = __ldg(tab + i111);
        }

        const float ux = 1.0f - wx;
        const float uy = 1.0f - wy;
        const float uz = 1.0f - wz;

        const float w000 = ux * uy * uz;
        const float w100 = wx * uy * uz;
        const float w010 = ux * wy * uz;
        const float w110 = wx * wy * uz;
        const float w001 = ux * uy * wz;
        const float w101 = wx * uy * wz;
        const float w011 = ux * wy * wz;
        const float w111 = wx * wy * wz;

        float acc0 = w000 * f000.x;
        float acc1 = w000 * f000.y;
        acc0 += w100 * f100.x;  acc1 += w100 * f100.y;
        acc0 += w010 * f010.x;  acc1 += w010 * f010.y;
        acc0 += w110 * f110.x;  acc1 += w110 * f110.y;
        acc0 += w001 * f001.x;  acc1 += w001 * f001.y;
        acc0 += w101 * f101.x;  acc1 += w101 * f101.y;
        acc0 += w011 * f011.x;  acc1 += w011 * f011.y;
        acc0 += w111 * f111.x;  acc1 += w111 * f111.y;

        if ((l & 1) == 0) {
            pend0 = acc0;
            pend1 = acc1;
        } else {
            __stcs(&o[l >> 1], make_float4(pend0, pend1, acc0, acc1));
        }
    }
}

extern "C" void kernel_launch(void* const* d_in, const int* in_sizes, int n_in,
                              void* d_out, int out_size) {
    const float* x      = (const float*)d_in[0];
    const float* tables = (const float*)d_in[1];
    float* out          = (float*)d_out;

    const int threads = 256;
    const int blocks      = (N_PTS + threads - 1) / threads;
    const int blocks_hist = (N_PTS / HIST_PPT + threads - 1) / threads;
    const int blocks_scat = (N_PTS / SCAT_PPT + threads - 1) / threads;

    static bool attr_set = false;
    if (!attr_set) {
        cudaFuncSetAttribute(scan_kernel,
                             cudaFuncAttributeMaxDynamicSharedMemorySize,
                             NB * sizeof(uint32_t));
        attr_set = true;
    }

    // Zero the histogram with a memset node (graph-capturable, no alloc).
    void* hist_ptr = nullptr;
    cudaGetSymbolAddress(&hist_ptr, g_hist);
    cudaMemsetAsync(hist_ptr, 0, NB * sizeof(uint32_t));

    hist_kernel<<<blocks_hist, threads>>>(x);
    scan_kernel<<<1, 1024, NB * sizeof(uint32_t)>>>();
    scatter_kernel<<<blocks_scat, threads>>>(x);
    hashgrid_kernel<<<blocks, threads>>>(tables, out);
}

// round 16
// speedup vs baseline: 1.0059x; 1.0059x over previous
#include <cuda_runtime.h>
#include <cstdint>

#define N_LEVELS 12
#define LOG2_T 19
#define TBL_SIZE (1u << LOG2_T)
#define TMASK (TBL_SIZE - 1u)
#define N_FEATURES 2
#define N_PTS 1048576

#define P1 2654435761u
#define P2 805459861u

#define SORT_RES 32
#define NB (SORT_RES * SORT_RES * SORT_RES)   // 32768 buckets, key = 15 bits

#define HIST_PPT 2     // points per thread in hist
#define SCAT_PPT 4     // points per thread in scatter

__device__ uint32_t g_kr[N_PTS];      // packed: key | (rank << 15)
__device__ uint32_t g_hist[NB];
__device__ uint32_t g_off[NB];
__device__ float4   g_xs[N_PTS];      // sorted points: (x, y, z, bits(orig_idx))

__device__ __forceinline__ uint32_t part1by2(uint32_t v) {
    v &= 0x3FFu;
    v = (v | (v << 16)) & 0x030000FFu;
    v = (v | (v << 8))  & 0x0300F00Fu;
    v = (v | (v << 4))  & 0x030C30C3u;
    v = (v | (v << 2))  & 0x09249249u;
    return v;
}

__device__ __forceinline__ uint32_t bucket_key(float px, float py, float pz) {
    uint32_t cx = min((uint32_t)(px * (float)SORT_RES), (uint32_t)(SORT_RES - 1));
    uint32_t cy = min((uint32_t)(py * (float)SORT_RES), (uint32_t)(SORT_RES - 1));
    uint32_t cz = min((uint32_t)(pz * (float)SORT_RES), (uint32_t)(SORT_RES - 1));
    return part1by2(cx) | (part1by2(cy) << 1) | (part1by2(cz) << 2);
}

// Key + intra-bucket rank (atomicAdd return), packed into one word.
__global__ void hist_kernel(const float* __restrict__ x) {
    const int t = blockIdx.x * blockDim.x + threadIdx.x;
    const int H = N_PTS / HIST_PPT;
    if (t >= H) return;

    const int i0 = t;
    const int i1 = t + H;

    const float ax = x[3 * i0 + 0];
    const float ay = x[3 * i0 + 1];
    const float az = x[3 * i0 + 2];
    const float bx = x[3 * i1 + 0];
    const float by = x[3 * i1 + 1];
    const float bz = x[3 * i1 + 2];

    const uint32_t ka = bucket_key(ax, ay, az);
    const uint32_t kb = bucket_key(bx, by, bz);

    const uint32_t ra = atomicAdd(&g_hist[ka], 1u);
    const uint32_t rb = atomicAdd(&g_hist[kb], 1u);

    g_kr[i0] = ka | (ra << 15);
    g_kr[i1] = kb | (rb << 15);
}

// Bank-swizzled smem index (round 5 notes).
__device__ __forceinline__ uint32_t swz(uint32_t i) {
    return (i & ~31u) | ((i + (i >> 5)) & 31u);
}

// Exclusive scan of 32768 bins; all global traffic coalesced via 128KB smem.
__global__ void __launch_bounds__(1024) scan_kernel() {
    extern __shared__ uint32_t sh[];
    __shared__ uint32_t s[1024];
    const int t = threadIdx.x;

    #pragma unroll
    for (int k = 0; k < 32; k++) {
        uint32_t i = (uint32_t)(k * 1024 + t);
        sh[swz(i)] = g_hist[i];
    }
    __syncthreads();

    uint32_t vals[32];
    uint32_t tot = 0;
    #pragma unroll
    for (int k = 0; k < 32; k++) {
        vals[k] = sh[t * 32 + ((k + t) & 31)];
        tot += vals[k];
    }
    s[t] = tot;
    __syncthreads();

    for (int off = 1; off < 1024; off <<= 1) {
        uint32_t v = (t >= off) ? s[t - off] : 0u;
        __syncthreads();
        s[t] += v;
        __syncthreads();
    }

    uint32_t run = s[t] - tot;
    #pragma unroll
    for (int k = 0; k < 32; k++) {
        sh[t * 32 + ((k + t) & 31)] = run;
        run += vals[k];
    }
    __syncthreads();

    #pragma unroll
    for (int k = 0; k < 32; k++) {
        uint32_t i = (uint32_t)(k * 1024 + t);
        g_off[i] = sh[swz(i)];
    }
}

// Atomic-free scatter, 4 points per thread. Rank order from hist's atomics is
// nondeterministic, but g_xs is always the same multiset and every point's
// output goes to its own original slot -> d_out is order-invariant.
__global__ void scatter_kernel(const float* __restrict__ x) {
    const int t = blockIdx.x * blockDim.x + threadIdx.x;
    const int Q = N_PTS / SCAT_PPT;
    if (t >= Q) return;

    int idx[SCAT_PPT];
    uint32_t kr[SCAT_PPT];
    #pragma unroll
    for (int k = 0; k < SCAT_PPT; k++) {
        idx[k] = t + k * Q;
        kr[k] = g_kr[idx[k]];
    }

    uint32_t base[SCAT_PPT];
    #pragma unroll
    for (int k = 0; k < SCAT_PPT; k++)
        base[k] = g_off[kr[k] & (NB - 1u)];

    float4 p[SCAT_PPT];
    #pragma unroll
    for (int k = 0; k < SCAT_PPT; k++) {
        p[k].x = x[3 * idx[k] + 0];
        p[k].y = x[3 * idx[k] + 1];
        p[k].z = x[3 * idx[k] + 2];
        p[k].w = __uint_as_float((uint32_t)idx[k]);
    }

    #pragma unroll
    for (int k = 0; k < SCAT_PPT; k++)
        __stcs(&g_xs[base[k] + (kr[k] >> 15)], p[k]);
}

__global__ void __launch_bounds__(256, 5) hashgrid_kernel(
    const float* __restrict__ tables,
    float* __restrict__ out)
{
    const int i = blockIdx.x * blockDim.x + threadIdx.x;
    if (i >= N_PTS) return;

    // One coalesced 16B load delivers coords + original index.
    const float4 p = __ldg(&g_xs[i]);
    const float px = p.x;
    const float py = p.y;
    const float pz = p.z;
    const uint32_t j = __float_as_uint(p.w);

    float4* __restrict__ o = (float4*)(out + (size_t)j * (N_LEVELS * N_FEATURES));

    // Process fine levels FIRST: their gathers are the long-latency ones
    // (L2/DRAM misses); issuing them at the top of the stream lets the
    // coarse levels' L1-hit work run in their latency shadow. Each pair
    // still writes its own output slot -> bit-identical results.
    const int lvl_order[N_LEVELS] = {8, 9, 10, 11, 0, 1, 2, 3, 4, 5, 6, 7};
    const int res_all[N_LEVELS] = {16, 22, 30, 42, 58, 80, 110, 152, 210, 290, 400, 553};

    float pend0 = 0.0f, pend1 = 0.0f;

    #pragma unroll
    for (int q = 0; q < N_LEVELS; q++) {
        const int l = lvl_order[q];
        const float res = (float)res_all[l];

        const float sx = px * res;
        const float sy = py * res;
        const float sz = pz * res;
        const float fx = floorf(sx);
        const float fy = floorf(sy);
        const float fz = floorf(sz);
        const float wx = sx - fx;
        const float wy = sy - fy;
        const float wz = sz - fz;

        const uint32_t xi = (uint32_t)fx;
        const uint32_t yi = (uint32_t)fy;
        const uint32_t zi = (uint32_t)fz;

        const uint32_t hy0 = yi * P1;
        const uint32_t hy1 = (yi + 1u) * P1;
        const uint32_t hz0 = zi * P2;
        const uint32_t hz1 = (zi + 1u) * P2;
        const uint32_t x0 = xi;
        const uint32_t x1 = xi + 1u;

        const uint32_t m00 = hy0 ^ hz0;
        const uint32_t m10 = hy1 ^ hz0;
        const uint32_t m01 = hy0 ^ hz1;
        const uint32_t m11 = hy1 ^ hz1;

        const uint32_t i000 = (x0 ^ m00) & TMASK;
        const uint32_t i010 = (x0 ^ m10) & TMASK;
        const uint32_t i001 = (x0 ^ m01) & TMASK;
        const uint32_t i011 = (x0 ^ m11) & TMASK;

        const float2* __restrict__ tab =
            (const float2*)(tables + (size_t)l * TBL_SIZE * N_FEATURES);

        float2 f000, f100, f010, f110, f001, f101, f011, f111;

        if ((xi & 1u) == 0u) {
            // x1 = x0 | 1: each dx-pair is consecutive entries {2k,2k+1}
            // -> one aligned float4 per pair.
            const float4* __restrict__ t4 = (const float4*)tab;
            const float4 v00 = __ldg(t4 + (i000 >> 1));
            const float4 v10 = __ldg(t4 + (i010 >> 1));
            const float4 v01 = __ldg(t4 + (i001 >> 1));
            const float4 v11 = __ldg(t4 + (i011 >> 1));

            const bool s00 = (i000 & 1u) != 0u;
            const bool s10 = (i010 & 1u) != 0u;
            const bool s01 = (i001 & 1u) != 0u;
            const bool s11 = (i011 & 1u) != 0u;

            f000 = s00 ? make_float2(v00.z, v00.w) : make_float2(v00.x, v00.y);
            f100 = s00 ? make_float2(v00.x, v00.y) : make_float2(v00.z, v00.w);
            f010 = s10 ? make_float2(v10.z, v10.w) : make_float2(v10.x, v10.y);
            f110 = s10 ? make_float2(v10.x, v10.y) : make_float2(v10.z, v10.w);
            f001 = s01 ? make_float2(v01.z, v01.w) : make_float2(v01.x, v01.y);
            f101 = s01 ? make_float2(v01.x, v01.y) : make_float2(v01.z, v01.w);
            f011 = s11 ? make_float2(v11.z, v11.w) : make_float2(v11.x, v11.y);
            f111 = s11 ? make_float2(v11.x, v11.y) : make_float2(v11.z, v11.w);
        } else {
            const uint32_t i100 = (x1 ^ m00) & TMASK;
            const uint32_t i110 = (x1 ^ m10) & TMASK;
            const uint32_t i101 = (x1 ^ m01) & TMASK;
            const uint32_t i111 = (x1 ^ m11) & TMASK;

            f000 = __ldg(tab + i000);
            f100 = __ldg(tab + i100);
            f010 = __ldg(tab + i010);
            f110 = __ldg(tab + i110);
            f001 = __ldg(tab + i001);
            f101 = __ldg(tab + i101);
            f011 = __ldg(tab + i011);
            f111 = __ldg(tab + i111);
        }

        const float ux = 1.0f - wx;
        const float uy = 1.0f - wy;
        const float uz = 1.0f - wz;

        const float w000 = ux * uy * uz;
        const float w100 = wx * uy * uz;
        const float w010 = ux * wy * uz;
        const float w110 = wx * wy * uz;
        const float w001 = ux * uy * wz;
        const float w101 = wx * uy * wz;
        const float w011 = ux * wy * wz;
        const float w111 = wx * wy * wz;

        float acc0 = w000 * f000.x;
        float acc1 = w000 * f000.y;
        acc0 += w100 * f100.x;  acc1 += w100 * f100.y;
        acc0 += w010 * f010.x;  acc1 += w010 * f010.y;
        acc0 += w110 * f110.x;  acc1 += w110 * f110.y;
        acc0 += w001 * f001.x;  acc1 += w001 * f001.y;
        acc0 += w101 * f101.x;  acc1 += w101 * f101.y;
        acc0 += w011 * f011.x;  acc1 += w011 * f011.y;
        acc0 += w111 * f111.x;  acc1 += w111 * f111.y;

        // l and its pair partner are processed consecutively; flush the
        // float4 for slot l>>1 when the odd member completes.
        if ((l & 1) == 0) {
            pend0 = acc0;
            pend1 = acc1;
        } else {
            __stcs(&o[l >> 1], make_float4(pend0, pend1, acc0, acc1));
        }
    }
}

extern "C" void kernel_launch(void* const* d_in, const int* in_sizes, int n_in,
                              void* d_out, int out_size) {
    const float* x      = (const float*)d_in[0];
    const float* tables = (const float*)d_in[1];
    float* out          = (float*)d_out;

    const int threads = 256;
    const int blocks      = (N_PTS + threads - 1) / threads;
    const int blocks_hist = (N_PTS / HIST_PPT + threads - 1) / threads;
    const int blocks_scat = (N_PTS / SCAT_PPT + threads - 1) / threads;

    static bool attr_set = false;
    if (!attr_set) {
        cudaFuncSetAttribute(scan_kernel,
                             cudaFuncAttributeMaxDynamicSharedMemorySize,
                             NB * sizeof(uint32_t));
        attr_set = true;
    }

    // Zero the histogram with a memset node (graph-capturable, no alloc).
    void* hist_ptr = nullptr;
    cudaGetSymbolAddress(&hist_ptr, g_hist);
    cudaMemsetAsync(hist_ptr, 0, NB * sizeof(uint32_t));

    hist_kernel<<<blocks_hist, threads>>>(x);
    scan_kernel<<<1, 1024, NB * sizeof(uint32_t)>>>();
    scatter_kernel<<<blocks_scat, threads>>>(x);
    hashgrid_kernel<<<blocks, threads>>>(tables, out);
}

// round 17
// speedup vs baseline: 1.0454x; 1.0392x over previous
#include <cuda_runtime.h>
#include <cstdint>

#define N_LEVELS 12
#define LOG2_T 19
#define TBL_SIZE (1u << LOG2_T)
#define TMASK (TBL_SIZE - 1u)
#define N_FEATURES 2
#define N_PTS 1048576

#define P1 2654435761u
#define P2 805459861u

#define SORT_RES 64
#define NB (SORT_RES * SORT_RES * SORT_RES)   // 262144 buckets, key = 18 bits
#define KEY_BITS 18
#define KEY_MASK ((1u << KEY_BITS) - 1u)
#define SEG 32768                              // bins per scan block
#define NSEG (NB / SEG)                        // 8 segments

__device__ uint32_t g_kr[N_PTS];      // packed: key | (rank << 18)
__device__ uint32_t g_hist[NB];
__device__ uint32_t g_off[NB];        // segment-local exclusive offsets
__device__ uint32_t g_segtot[NSEG];
__device__ uint32_t g_segoff[NSEG];
__device__ float4   g_xs[N_PTS];      // sorted points: (x, y, z, bits(orig_idx))

__device__ __forceinline__ uint32_t part1by2(uint32_t v) {
    v &= 0x3FFu;
    v = (v | (v << 16)) & 0x030000FFu;
    v = (v | (v << 8))  & 0x0300F00Fu;
    v = (v | (v << 4))  & 0x030C30C3u;
    v = (v | (v << 2))  & 0x09249249u;
    return v;
}

__device__ __forceinline__ uint32_t bucket_key(float px, float py, float pz) {
    uint32_t cx = min((uint32_t)(px * (float)SORT_RES), (uint32_t)(SORT_RES - 1));
    uint32_t cy = min((uint32_t)(py * (float)SORT_RES), (uint32_t)(SORT_RES - 1));
    uint32_t cz = min((uint32_t)(pz * (float)SORT_RES), (uint32_t)(SORT_RES - 1));
    return part1by2(cx) | (part1by2(cy) << 1) | (part1by2(cz) << 2);
}

// Key + intra-bucket rank (atomicAdd return), packed into one word.
// Rank <= ~30 (Poisson, mean 4) fits easily in 32-18=14 bits.
__global__ void hist_kernel(const float* __restrict__ x) {
    int i = blockIdx.x * blockDim.x + threadIdx.x;
    if (i >= N_PTS) return;
    uint32_t key = bucket_key(x[3 * i], x[3 * i + 1], x[3 * i + 2]);
    uint32_t rank = atomicAdd(&g_hist[key], 1u);
    g_kr[i] = key | (rank << KEY_BITS);
}

// Bank-swizzled smem index (round 5 notes).
__device__ __forceinline__ uint32_t swz(uint32_t i) {
    return (i & ~31u) | ((i + (i >> 5)) & 31u);
}

// Segmented exclusive scan: each of NSEG blocks scans its 32768-bin segment
// through a 128KB smem staging buffer (verified-coalesced pattern), writing
// segment-local exclusive offsets + its segment total.
__global__ void __launch_bounds__(1024) scan_kernel() {
    extern __shared__ uint32_t sh[];
    __shared__ uint32_t s[1024];
    const int t = threadIdx.x;
    const uint32_t segbase = (uint32_t)blockIdx.x * SEG;

    #pragma unroll
    for (int k = 0; k < 32; k++) {
        uint32_t i = (uint32_t)(k * 1024 + t);
        sh[swz(i)] = g_hist[segbase + i];
    }
    __syncthreads();

    uint32_t vals[32];
    uint32_t tot = 0;
    #pragma unroll
    for (int k = 0; k < 32; k++) {
        vals[k] = sh[t * 32 + ((k + t) & 31)];
        tot += vals[k];
    }
    s[t] = tot;
    __syncthreads();

    for (int off = 1; off < 1024; off <<= 1) {
        uint32_t v = (t >= off) ? s[t - off] : 0u;
        __syncthreads();
        s[t] += v;
        __syncthreads();
    }

    if (t == 1023) g_segtot[blockIdx.x] = s[1023];

    uint32_t run = s[t] - tot;
    #pragma unroll
    for (int k = 0; k < 32; k++) {
        sh[t * 32 + ((k + t) & 31)] = run;
        run += vals[k];
    }
    __syncthreads();

    #pragma unroll
    for (int k = 0; k < 32; k++) {
        uint32_t i = (uint32_t)(k * 1024 + t);
        g_off[segbase + i] = sh[swz(i)];
    }
}

// Tiny pass: exclusive scan of the NSEG segment totals.
__global__ void segscan_kernel() {
    if (threadIdx.x == 0) {
        uint32_t run = 0;
        #pragma unroll
        for (int k = 0; k < NSEG; k++) {
            g_segoff[k] = run;
            run += g_segtot[k];
        }
    }
}

// Atomic-free scatter: pos = segment offset + local bucket offset + rank.
// Rank order from hist's atomics is nondeterministic, but g_xs is always the
// same multiset and every point's output goes to its own original slot
// -> d_out is order-invariant.
__global__ void scatter_kernel(const float* __restrict__ x) {
    int i = blockIdx.x * blockDim.x + threadIdx.x;
    if (i >= N_PTS) return;
    uint32_t v = g_kr[i];
    uint32_t key = v & KEY_MASK;
    uint32_t pos = g_segoff[key >> 15] + g_off[key] + (v >> KEY_BITS);
    float4 p;
    p.x = x[3 * i + 0];
    p.y = x[3 * i + 1];
    p.z = x[3 * i + 2];
    p.w = __uint_as_float((uint32_t)i);
    __stcs(&g_xs[pos], p);
}

__global__ void __launch_bounds__(256, 5) hashgrid_kernel(
    const float* __restrict__ tables,
    float* __restrict__ out)
{
    const int i = blockIdx.x * blockDim.x + threadIdx.x;
    if (i >= N_PTS) return;

    // One coalesced 16B load delivers coords + original index.
    const float4 p = __ldg(&g_xs[i]);
    const float px = p.x;
    const float py = p.y;
    const float pz = p.z;
    const uint32_t j = __float_as_uint(p.w);

    float4* __restrict__ o = (float4*)(out + (size_t)j * (N_LEVELS * N_FEATURES));

    const int res_host[N_LEVELS] = {16, 22, 30, 42, 58, 80, 110, 152, 210, 290, 400, 553};

    float pend0 = 0.0f, pend1 = 0.0f;

    #pragma unroll
    for (int l = 0; l < N_LEVELS; l++) {
        const float res = (float)res_host[l];

        const float sx = px * res;
        const float sy = py * res;
        const float sz = pz * res;
        const float fx = floorf(sx);
        const float fy = floorf(sy);
        const float fz = floorf(sz);
        const float wx = sx - fx;
        const float wy = sy - fy;
        const float wz = sz - fz;

        const uint32_t xi = (uint32_t)fx;
        const uint32_t yi = (uint32_t)fy;
        const uint32_t zi = (uint32_t)fz;

        const uint32_t hy0 = yi * P1;
        const uint32_t hy1 = (yi + 1u) * P1;
        const uint32_t hz0 = zi * P2;
        const uint32_t hz1 = (zi + 1u) * P2;
        const uint32_t x0 = xi;
        const uint32_t x1 = xi + 1u;

        const uint32_t m00 = hy0 ^ hz0;
        const uint32_t m10 = hy1 ^ hz0;
        const uint32_t m01 = hy0 ^ hz1;
        const uint32_t m11 = hy1 ^ hz1;

        const uint32_t i000 = (x0 ^ m00) & TMASK;
        const uint32_t i010 = (x0 ^ m10) & TMASK;
        const uint32_t i001 = (x0 ^ m01) & TMASK;
        const uint32_t i011 = (x0 ^ m11) & TMASK;

        const float2* __restrict__ tab =
            (const float2*)(tables + (size_t)l * TBL_SIZE * N_FEATURES);

        float2 f000, f100, f010, f110, f001, f101, f011, f111;

        if ((xi & 1u) == 0u) {
            // x1 = x0 | 1: each dx-pair is consecutive entries {2k,2k+1}
            // -> one aligned float4 per pair.
            const float4* __restrict__ t4 = (const float4*)tab;
            const float4 v00 = __ldg(t4 + (i000 >> 1));
            const float4 v10 = __ldg(t4 + (i010 >> 1));
            const float4 v01 = __ldg(t4 + (i001 >> 1));
            const float4 v11 = __ldg(t4 + (i011 >> 1));

            const bool s00 = (i000 & 1u) != 0u;
            const bool s10 = (i010 & 1u) != 0u;
            const bool s01 = (i001 & 1u) != 0u;
            const bool s11 = (i011 & 1u) != 0u;

            f000 = s00 ? make_float2(v00.z, v00.w) : make_float2(v00.x, v00.y);
            f100 = s00 ? make_float2(v00.x, v00.y) : make_float2(v00.z, v00.w);
            f010 = s10 ? make_float2(v10.z, v10.w) : make_float2(v10.x, v10.y);
            f110 = s10 ? make_float2(v10.x, v10.y) : make_float2(v10.z, v10.w);
            f001 = s01 ? make_float2(v01.z, v01.w) : make_float2(v01.x, v01.y);
            f101 = s01 ? make_float2(v01.x, v01.y) : make_float2(v01.z, v01.w);
            f011 = s11 ? make_float2(v11.z, v11.w) : make_float2(v11.x, v11.y);
            f111 = s11 ? make_float2(v11.x, v11.y) : make_float2(v11.z, v11.w);
        } else {
            const uint32_t i100 = (x1 ^ m00) & TMASK;
            const uint32_t i110 = (x1 ^ m10) & TMASK;
            const uint32_t i101 = (x1 ^ m01) & TMASK;
            const uint32_t i111 = (x1 ^ m11) & TMASK;

            f000 = __ldg(tab + i000);
            f100 = __ldg(tab + i100);
            f010 = __ldg(tab + i010);
            f110 = __ldg(tab + i110);
            f001 = __ldg(tab + i001);
            f101 = __ldg(tab + i101);
            f011 = __ldg(tab + i011);
            f111 = __ldg(tab + i111);
        }

        const float ux = 1.0f - wx;
        const float uy = 1.0f - wy;
        const float uz = 1.0f - wz;

        const float w000 = ux * uy * uz;
        const float w100 = wx * uy * uz;
        const float w010 = ux * wy * uz;
        const float w110 = wx * wy * uz;
        const float w001 = ux * uy * wz;
        const float w101 = wx * uy * wz;
        const float w011 = ux * wy * wz;
        const float w111 = wx * wy * wz;

        float acc0 = w000 * f000.x;
        float acc1 = w000 * f000.y;
        acc0 += w100 * f100.x;  acc1 += w100 * f100.y;
        acc0 += w010 * f010.x;  acc1 += w010 * f010.y;
        acc0 += w110 * f110.x;  acc1 += w110 * f110.y;
        acc0 += w001 * f001.x;  acc1 += w001 * f001.y;
        acc0 += w101 * f101.x;  acc1 += w101 * f101.y;
        acc0 += w011 * f011.x;  acc1 += w011 * f011.y;
        acc0 += w111 * f111.x;  acc1 += w111 * f111.y;

        if ((l & 1) == 0) {
            pend0 = acc0;
            pend1 = acc1;
        } else {
            __stcs(&o[l >> 1], make_float4(pend0, pend1, acc0, acc1));
        }
    }
}

extern "C" void kernel_launch(void* const* d_in, const int* in_sizes, int n_in,
                              void* d_out, int out_size) {
    const float* x      = (const float*)d_in[0];
    const float* tables = (const float*)d_in[1];
    float* out          = (float*)d_out;

    const int threads = 256;
    const int blocks = (N_PTS + threads - 1) / threads;

    static bool attr_set = false;
    if (!attr_set) {
        cudaFuncSetAttribute(scan_kernel,
                             cudaFuncAttributeMaxDynamicSharedMemorySize,
                             SEG * sizeof(uint32_t));
        attr_set = true;
    }

    // Zero the histogram with a memset node (graph-capturable, no alloc).
    void* hist_ptr = nullptr;
    cudaGetSymbolAddress(&hist_ptr, g_hist);
    cudaMemsetAsync(hist_ptr, 0, NB * sizeof(uint32_t));

    hist_kernel<<<blocks, threads>>>(x);
    scan_kernel<<<NSEG, 1024, SEG * sizeof(uint32_t)>>>();
    segscan_kernel<<<1, 32>>>();
    scatter_kernel<<<blocks, threads>>>(x);
    hashgrid_kernel<<<blocks, threads>>>(tables, out);
}